// round 4
// baseline (speedup 1.0000x reference)
#include <cuda_runtime.h>
#include <cuda_bf16.h>
#include <cstdint>

#define NN 100000
#define NE 1600000
#define DD 128

// ---------------- scratch (static device allocations) ----------------
__device__ int   g_is64;             // 1 if edge_index is int64, 0 if int32
__device__ int   g_cnt[NN];          // per-dst edge count (no self-loop)
__device__ int   g_rowstart[NN + 1]; // CSC row offsets
__device__ int   g_cursor[NN];       // scatter cursors
__device__ float g_dinv[NN];         // deg^{-1/2} (deg includes self-loop)
__device__ int   g_src_sorted[NE];   // src per sorted edge
__device__ float g_norm_sorted[NE];  // norm per sorted edge
__device__ float4 g_h1[(size_t)NN * 32];
__device__ float4 g_h2[(size_t)NN * 32];

// ---------------- 0) detect edge_index dtype ----------------
// int64 little-endian with values < 2^31: every odd 32-bit word is 0.
// int32 random indices in [0, NN): essentially impossible for 512 odd words
// to all be zero.
__global__ void detect_kernel(const unsigned int* __restrict__ e) {
    if (blockIdx.x == 0 && threadIdx.x == 0) {
        unsigned int odd_or = 0u;
        for (int i = 1; i < 2048; i += 2) odd_or |= e[i];
        g_is64 = (odd_or == 0u) ? 1 : 0;
    }
}

__device__ __forceinline__ int load_idx(const void* ei, long long pos) {
    if (g_is64) {
        long long v = ((const long long*)ei)[pos];
        return (int)v;
    } else {
        return ((const int*)ei)[pos];
    }
}

// ---------------- 1) zero counters ----------------
__global__ void zero_cnt_kernel() {
    int i = blockIdx.x * blockDim.x + threadIdx.x;
    if (i < NN) g_cnt[i] = 0;
}

// ---------------- 2) histogram of dst ----------------
__global__ void hist_kernel(const void* __restrict__ ei) {
    int i = blockIdx.x * blockDim.x + threadIdx.x;
    if (i < NE) {
        int d = load_idx(ei, (long long)NE + i);
        if ((unsigned)d < (unsigned)NN) atomicAdd(&g_cnt[d], 1);
    }
}

// ---------------- 3) dinv = rsqrt(deg + 1 selfloop) ----------------
__global__ void dinv_kernel() {
    int i = blockIdx.x * blockDim.x + threadIdx.x;
    if (i < NN) {
        g_dinv[i] = rsqrtf((float)(g_cnt[i] + 1));
    }
}

// ---------------- 4) exclusive scan (single block, 1024 threads) ----------------
__global__ void scan_kernel() {
    __shared__ int part[1024];
    const int T = 1024;
    int t = threadIdx.x;
    const int chunk = (NN + T - 1) / T; // 98
    int begin = t * chunk;
    int end   = begin + chunk; if (end > NN) end = NN;
    if (begin > NN) begin = NN;

    int s = 0;
    for (int i = begin; i < end; i++) s += g_cnt[i];
    part[t] = s;
    __syncthreads();
    // Hillis-Steele inclusive scan
    for (int off = 1; off < T; off <<= 1) {
        int v = (t >= off) ? part[t - off] : 0;
        __syncthreads();
        part[t] += v;
        __syncthreads();
    }
    int run = (t == 0) ? 0 : part[t - 1];
    for (int i = begin; i < end; i++) {
        int c = g_cnt[i];
        g_rowstart[i] = run;
        g_cursor[i]   = run;
        run += c;
    }
    if (t == T - 1) g_rowstart[NN] = part[T - 1];
}

// ---------------- 5) scatter edges into CSC order ----------------
__global__ void scatter_kernel(const void* __restrict__ ei) {
    int i = blockIdx.x * blockDim.x + threadIdx.x;
    if (i < NE) {
        int s = load_idx(ei, i);
        int d = load_idx(ei, (long long)NE + i);
        if ((unsigned)s < (unsigned)NN && (unsigned)d < (unsigned)NN) {
            int p = atomicAdd(&g_cursor[d], 1);
            g_src_sorted[p]  = s;
            g_norm_sorted[p] = g_dinv[s] * g_dinv[d];
        }
    }
}

// ---------------- 6) propagation: one warp per destination node ----------------
__device__ __forceinline__ void prop_body(const float4* __restrict__ hin,
                                          float4* __restrict__ hout) {
    int gtid = blockIdx.x * blockDim.x + threadIdx.x;
    int v    = gtid >> 5;
    int lane = gtid & 31;
    if (v >= NN) return;

    float d  = g_dinv[v];
    float dd = d * d;
    float4 hv  = hin[(size_t)v * 32 + lane];
    float4 acc;
    acc.x = dd * hv.x; acc.y = dd * hv.y; acc.z = dd * hv.z; acc.w = dd * hv.w;

    int e  = g_rowstart[v];
    int e1 = g_rowstart[v + 1];

    for (; e + 4 <= e1; e += 4) {
        int   s0 = __ldg(&g_src_sorted[e]);
        int   s1 = __ldg(&g_src_sorted[e + 1]);
        int   s2 = __ldg(&g_src_sorted[e + 2]);
        int   s3 = __ldg(&g_src_sorted[e + 3]);
        float w0 = __ldg(&g_norm_sorted[e]);
        float w1 = __ldg(&g_norm_sorted[e + 1]);
        float w2 = __ldg(&g_norm_sorted[e + 2]);
        float w3 = __ldg(&g_norm_sorted[e + 3]);
        float4 a0 = __ldg(&hin[(size_t)s0 * 32 + lane]);
        float4 a1 = __ldg(&hin[(size_t)s1 * 32 + lane]);
        float4 a2 = __ldg(&hin[(size_t)s2 * 32 + lane]);
        float4 a3 = __ldg(&hin[(size_t)s3 * 32 + lane]);
        acc.x += w0 * a0.x; acc.y += w0 * a0.y; acc.z += w0 * a0.z; acc.w += w0 * a0.w;
        acc.x += w1 * a1.x; acc.y += w1 * a1.y; acc.z += w1 * a1.z; acc.w += w1 * a1.w;
        acc.x += w2 * a2.x; acc.y += w2 * a2.y; acc.z += w2 * a2.z; acc.w += w2 * a2.w;
        acc.x += w3 * a3.x; acc.y += w3 * a3.y; acc.z += w3 * a3.z; acc.w += w3 * a3.w;
    }
    for (; e < e1; e++) {
        int   s = __ldg(&g_src_sorted[e]);
        float w = __ldg(&g_norm_sorted[e]);
        float4 a = __ldg(&hin[(size_t)s * 32 + lane]);
        acc.x += w * a.x; acc.y += w * a.y; acc.z += w * a.z; acc.w += w * a.w;
    }
    hout[(size_t)v * 32 + lane] = acc;
}

// hop 1: external x -> g_h1
__global__ void __launch_bounds__(256) prop1_kernel(const float4* __restrict__ x) {
    prop_body(x, g_h1);
}
// hop 2: g_h1 -> g_h2
__global__ void __launch_bounds__(256) prop2_kernel() {
    prop_body(g_h1, g_h2);
}

// ---------------- 7) GEMM: out = g_h2 @ W + b ----------------
// Block: 64 rows x 128 cols, 256 threads. Each thread: 8 rows x 4 cols.
__global__ void __launch_bounds__(256) gemm_kernel(const float* __restrict__ Wm,
                                                   const float* __restrict__ bias,
                                                   float* __restrict__ out) {
    __shared__ float xs[64][32];
    __shared__ float ws[32][128];

    const float* A = (const float*)g_h2;

    int tid = threadIdx.x;
    int row0 = blockIdx.x * 64;
    int colBase = (tid & 31) * 4;   // 0..124
    int rowBase = (tid >> 5) * 8;   // 0..56

    float acc[8][4];
#pragma unroll
    for (int r = 0; r < 8; r++)
#pragma unroll
        for (int c = 0; c < 4; c++) acc[r][c] = 0.0f;

    for (int kc = 0; kc < 4; kc++) {
        // load x tile 64x32 (8 elems per thread)
#pragma unroll
        for (int j = 0; j < 8; j++) {
            int idx = tid + j * 256;
            int r = idx >> 5;        // /32
            int k = idx & 31;
            int grow = row0 + r;
            xs[r][k] = (grow < NN) ? A[(size_t)grow * DD + kc * 32 + k] : 0.0f;
        }
        // load W tile 32x128 (16 elems per thread)
#pragma unroll
        for (int j = 0; j < 16; j++) {
            int idx = tid + j * 256;
            int kk = idx >> 7;       // /128
            int c  = idx & 127;
            ws[kk][c] = Wm[(size_t)(kc * 32 + kk) * DD + c];
        }
        __syncthreads();
#pragma unroll
        for (int k = 0; k < 32; k++) {
            float4 wf = *(const float4*)&ws[k][colBase];
#pragma unroll
            for (int r = 0; r < 8; r++) {
                float a = xs[rowBase + r][k];
                acc[r][0] += a * wf.x;
                acc[r][1] += a * wf.y;
                acc[r][2] += a * wf.z;
                acc[r][3] += a * wf.w;
            }
        }
        __syncthreads();
    }

    float4 bv = *(const float4*)&bias[colBase];
#pragma unroll
    for (int r = 0; r < 8; r++) {
        int grow = row0 + rowBase + r;
        if (grow < NN) {
            float4 o;
            o.x = acc[r][0] + bv.x;
            o.y = acc[r][1] + bv.y;
            o.z = acc[r][2] + bv.z;
            o.w = acc[r][3] + bv.w;
            *(float4*)&out[(size_t)grow * DD + colBase] = o;
        }
    }
}

// ---------------- launch ----------------
extern "C" void kernel_launch(void* const* d_in, const int* in_sizes, int n_in,
                              void* d_out, int out_size) {
    const float* x   = (const float*)d_in[0];
    const void*  ei  = d_in[1];
    const float* Wm  = (const float*)d_in[2];
    const float* bia = (const float*)d_in[3];
    float*       out = (float*)d_out;

    detect_kernel<<<1, 32>>>((const unsigned int*)ei);
    zero_cnt_kernel<<<(NN + 255) / 256, 256>>>();
    hist_kernel<<<(NE + 255) / 256, 256>>>(ei);
    dinv_kernel<<<(NN + 255) / 256, 256>>>();
    scan_kernel<<<1, 1024>>>();
    scatter_kernel<<<(NE + 255) / 256, 256>>>(ei);

    // 2 hops of propagation
    int prop_blocks = (NN * 32 + 255) / 256;  // one warp per node
    prop1_kernel<<<prop_blocks, 256>>>((const float4*)x);
    prop2_kernel<<<prop_blocks, 256>>>();

    // final linear
    gemm_kernel<<<(NN + 63) / 64, 256>>>(Wm, bia, out);
}

// round 5
// speedup vs baseline: 1.2277x; 1.2277x over previous
#include <cuda_runtime.h>
#include <cuda_fp16.h>
#include <cstdint>

#define NN 100000
#define NE 1600000
#define DD 128

// ---------------- scratch ----------------
__device__ int   g_is64;
__device__ int   g_cnt[NN];
__device__ int   g_rowstart[NN + 1];
__device__ int   g_cursor[NN];
__device__ float g_dinv[NN];
__device__ int   g_src_sorted[NE];
__device__ uint2  g_h0h[(size_t)NN * 32];  // x_hat = dinv*x, fp16 (4 halves per uint2)
__device__ uint2  g_h1h[(size_t)NN * 32];  // h1_hat = dinv*h1, fp16
__device__ float4 g_h2[(size_t)NN * 32];   // h2, fp32

// ---------------- helpers ----------------
__device__ __forceinline__ float4 unpack_h4(uint2 u) {
    __half2 p0 = *(__half2*)&u.x;
    __half2 p1 = *(__half2*)&u.y;
    float2 f0 = __half22float2(p0);
    float2 f1 = __half22float2(p1);
    return make_float4(f0.x, f0.y, f1.x, f1.y);
}
__device__ __forceinline__ uint2 pack_h4(float a, float b, float c, float d) {
    __half2 p0 = __floats2half2_rn(a, b);
    __half2 p1 = __floats2half2_rn(c, d);
    uint2 u;
    u.x = *(unsigned*)&p0;
    u.y = *(unsigned*)&p1;
    return u;
}
__device__ __forceinline__ int load_idx(const void* ei, long long pos) {
    if (g_is64) return (int)((const long long*)ei)[pos];
    return ((const int*)ei)[pos];
}

// ---------------- 1) init: zero counters + dtype detect ----------------
__global__ void init_kernel(const unsigned int* __restrict__ e) {
    int i = blockIdx.x * blockDim.x + threadIdx.x;
    if (i < NN) g_cnt[i] = 0;
    if (blockIdx.x == 0 && threadIdx.x == 0) {
        unsigned int odd_or = 0u;
        for (int j = 1; j < 2048; j += 2) odd_or |= e[j];
        g_is64 = (odd_or == 0u) ? 1 : 0;
    }
}

// ---------------- 2) histogram of dst ----------------
__global__ void hist_kernel(const void* __restrict__ ei) {
    int i = blockIdx.x * blockDim.x + threadIdx.x;
    if (i < NE) {
        int d = load_idx(ei, (long long)NE + i);
        if ((unsigned)d < (unsigned)NN) atomicAdd(&g_cnt[d], 1);
    }
}

// ---------------- 3) dinv + prescale x_hat = dinv*x (fp16) ----------------
__global__ void __launch_bounds__(256) scale_kernel(const float4* __restrict__ x) {
    int g = blockIdx.x * blockDim.x + threadIdx.x;
    int v = g >> 5, lane = g & 31;
    if (v >= NN) return;
    float dinv = rsqrtf((float)(g_cnt[v] + 1));
    if (lane == 0) g_dinv[v] = dinv;
    float4 a = x[(size_t)v * 32 + lane];
    g_h0h[(size_t)v * 32 + lane] = pack_h4(a.x * dinv, a.y * dinv, a.z * dinv, a.w * dinv);
}

// ---------------- 4) exclusive scan ----------------
__global__ void scan_kernel() {
    __shared__ int part[1024];
    const int T = 1024;
    int t = threadIdx.x;
    const int chunk = (NN + T - 1) / T;
    int begin = t * chunk;
    int end = begin + chunk; if (end > NN) end = NN;
    if (begin > NN) begin = NN;
    int s = 0;
    for (int i = begin; i < end; i++) s += g_cnt[i];
    part[t] = s;
    __syncthreads();
    for (int off = 1; off < T; off <<= 1) {
        int v = (t >= off) ? part[t - off] : 0;
        __syncthreads();
        part[t] += v;
        __syncthreads();
    }
    int run = (t == 0) ? 0 : part[t - 1];
    for (int i = begin; i < end; i++) {
        int c = g_cnt[i];
        g_rowstart[i] = run;
        g_cursor[i] = run;
        run += c;
    }
    if (t == T - 1) g_rowstart[NN] = part[T - 1];
}

// ---------------- 5) scatter edges (src only; norm-free) ----------------
__global__ void scatter_kernel(const void* __restrict__ ei) {
    int i = blockIdx.x * blockDim.x + threadIdx.x;
    if (i < NE) {
        int s = load_idx(ei, i);
        int d = load_idx(ei, (long long)NE + i);
        if ((unsigned)s < (unsigned)NN && (unsigned)d < (unsigned)NN) {
            int p = atomicAdd(&g_cursor[d], 1);
            g_src_sorted[p] = s;
        }
    }
}

// ---------------- 6) propagation, warp per node, fp16 gather ----------------
// hop1: h1_hat[v] = dinv[v]^2 * (x_hat[v] + sum x_hat[src])   (fp16 out)
__global__ void __launch_bounds__(256) prop1_kernel() {
    int g = blockIdx.x * blockDim.x + threadIdx.x;
    int v = g >> 5, lane = g & 31;
    if (v >= NN) return;
    float d = g_dinv[v];
    float sc = d * d;
    float4 acc = unpack_h4(g_h0h[(size_t)v * 32 + lane]);
    int e = g_rowstart[v], e1 = g_rowstart[v + 1];
    for (; e + 4 <= e1; e += 4) {
        int s0 = __ldg(&g_src_sorted[e]);
        int s1 = __ldg(&g_src_sorted[e + 1]);
        int s2 = __ldg(&g_src_sorted[e + 2]);
        int s3 = __ldg(&g_src_sorted[e + 3]);
        float4 a0 = unpack_h4(__ldg(&g_h0h[(size_t)s0 * 32 + lane]));
        float4 a1 = unpack_h4(__ldg(&g_h0h[(size_t)s1 * 32 + lane]));
        float4 a2 = unpack_h4(__ldg(&g_h0h[(size_t)s2 * 32 + lane]));
        float4 a3 = unpack_h4(__ldg(&g_h0h[(size_t)s3 * 32 + lane]));
        acc.x += a0.x + a1.x + a2.x + a3.x;
        acc.y += a0.y + a1.y + a2.y + a3.y;
        acc.z += a0.z + a1.z + a2.z + a3.z;
        acc.w += a0.w + a1.w + a2.w + a3.w;
    }
    for (; e < e1; e++) {
        int s = __ldg(&g_src_sorted[e]);
        float4 a = unpack_h4(__ldg(&g_h0h[(size_t)s * 32 + lane]));
        acc.x += a.x; acc.y += a.y; acc.z += a.z; acc.w += a.w;
    }
    g_h1h[(size_t)v * 32 + lane] = pack_h4(acc.x * sc, acc.y * sc, acc.z * sc, acc.w * sc);
}

// hop2: h2[v] = dinv[v] * (h1_hat[v] + sum h1_hat[src])   (fp32 out)
__global__ void __launch_bounds__(256) prop2_kernel() {
    int g = blockIdx.x * blockDim.x + threadIdx.x;
    int v = g >> 5, lane = g & 31;
    if (v >= NN) return;
    float sc = g_dinv[v];
    float4 acc = unpack_h4(g_h1h[(size_t)v * 32 + lane]);
    int e = g_rowstart[v], e1 = g_rowstart[v + 1];
    for (; e + 4 <= e1; e += 4) {
        int s0 = __ldg(&g_src_sorted[e]);
        int s1 = __ldg(&g_src_sorted[e + 1]);
        int s2 = __ldg(&g_src_sorted[e + 2]);
        int s3 = __ldg(&g_src_sorted[e + 3]);
        float4 a0 = unpack_h4(__ldg(&g_h1h[(size_t)s0 * 32 + lane]));
        float4 a1 = unpack_h4(__ldg(&g_h1h[(size_t)s1 * 32 + lane]));
        float4 a2 = unpack_h4(__ldg(&g_h1h[(size_t)s2 * 32 + lane]));
        float4 a3 = unpack_h4(__ldg(&g_h1h[(size_t)s3 * 32 + lane]));
        acc.x += a0.x + a1.x + a2.x + a3.x;
        acc.y += a0.y + a1.y + a2.y + a3.y;
        acc.z += a0.z + a1.z + a2.z + a3.z;
        acc.w += a0.w + a1.w + a2.w + a3.w;
    }
    for (; e < e1; e++) {
        int s = __ldg(&g_src_sorted[e]);
        float4 a = unpack_h4(__ldg(&g_h1h[(size_t)s * 32 + lane]));
        acc.x += a.x; acc.y += a.y; acc.z += a.z; acc.w += a.w;
    }
    g_h2[(size_t)v * 32 + lane] = make_float4(acc.x * sc, acc.y * sc, acc.z * sc, acc.w * sc);
}

// ---------------- 7) GEMM via tf32 mma with 3-term split ----------------
#define AS_STRIDE 132
#define WS_STRIDE 136
#define GEMM_SMEM_BYTES ((64 * AS_STRIDE + 128 * WS_STRIDE) * 4)

__device__ __forceinline__ void mma8(float c[4], const unsigned a[4], const unsigned b[2]) {
    asm volatile(
        "mma.sync.aligned.m16n8k8.row.col.f32.tf32.tf32.f32 "
        "{%0,%1,%2,%3}, {%4,%5,%6,%7}, {%8,%9}, {%0,%1,%2,%3};\n"
        : "+f"(c[0]), "+f"(c[1]), "+f"(c[2]), "+f"(c[3])
        : "r"(a[0]), "r"(a[1]), "r"(a[2]), "r"(a[3]), "r"(b[0]), "r"(b[1]));
}
__device__ __forceinline__ void split_tf32(float x, unsigned& hi, unsigned& lo) {
    unsigned h;
    asm("cvt.rna.tf32.f32 %0, %1;" : "=r"(h) : "f"(x));
    hi = h;
    lo = __float_as_uint(x - __uint_as_float(h));
}

__global__ void __launch_bounds__(256) gemm_kernel(const float4* __restrict__ Wm,
                                                   const float* __restrict__ bias,
                                                   float* __restrict__ out) {
    extern __shared__ float smem[];
    float* As = smem;                       // [64][AS_STRIDE]
    float* Ws = smem + 64 * AS_STRIDE;      // [128][WS_STRIDE]

    int tid = threadIdx.x;
    int row0 = blockIdx.x * 64;

    // load W tile 128x128 (16 float4 per thread)
#pragma unroll
    for (int j = 0; j < 16; j++) {
        int idx = tid + j * 256;           // float4 index 0..4095
        int r = idx >> 5;
        int c4 = idx & 31;
        float4 w = __ldg(&Wm[idx]);
        *(float4*)&Ws[r * WS_STRIDE + c4 * 4] = w;
    }
    // load A tile 64x128 (8 float4 per thread)
    const float4* A4 = (const float4*)g_h2;
#pragma unroll
    for (int j = 0; j < 8; j++) {
        int idx = tid + j * 256;           // 0..2047
        int r = idx >> 5;
        int c4 = idx & 31;
        int gr = row0 + r;
        float4 a = (gr < NN) ? A4[(size_t)gr * 32 + c4] : make_float4(0.f, 0.f, 0.f, 0.f);
        *(float4*)&As[r * AS_STRIDE + c4 * 4] = a;
    }
    __syncthreads();

    int warp = tid >> 5, lane = tid & 31;
    int mwarp = warp & 1, nwarp = warp >> 1;
    int m0 = mwarp * 32, n0 = nwarp * 32;
    int lr = lane >> 2, lc = lane & 3;

    float c[2][4][4];
#pragma unroll
    for (int mt = 0; mt < 2; mt++)
#pragma unroll
        for (int nt = 0; nt < 4; nt++)
#pragma unroll
            for (int i = 0; i < 4; i++) c[mt][nt][i] = 0.f;

    for (int k0 = 0; k0 < 128; k0 += 8) {
        unsigned ahi[2][4], alo[2][4];
#pragma unroll
        for (int mt = 0; mt < 2; mt++) {
            int mb = m0 + mt * 16;
            float a0 = As[(mb + lr) * AS_STRIDE + k0 + lc];
            float a1 = As[(mb + lr + 8) * AS_STRIDE + k0 + lc];
            float a2 = As[(mb + lr) * AS_STRIDE + k0 + lc + 4];
            float a3 = As[(mb + lr + 8) * AS_STRIDE + k0 + lc + 4];
            split_tf32(a0, ahi[mt][0], alo[mt][0]);
            split_tf32(a1, ahi[mt][1], alo[mt][1]);
            split_tf32(a2, ahi[mt][2], alo[mt][2]);
            split_tf32(a3, ahi[mt][3], alo[mt][3]);
        }
        unsigned bhi[4][2], blo[4][2];
#pragma unroll
        for (int nt = 0; nt < 4; nt++) {
            int nb = n0 + nt * 8;
            float b0 = Ws[(k0 + lc) * WS_STRIDE + nb + lr];
            float b1 = Ws[(k0 + lc + 4) * WS_STRIDE + nb + lr];
            split_tf32(b0, bhi[nt][0], blo[nt][0]);
            split_tf32(b1, bhi[nt][1], blo[nt][1]);
        }
#pragma unroll
        for (int mt = 0; mt < 2; mt++)
#pragma unroll
            for (int nt = 0; nt < 4; nt++) {
                mma8(c[mt][nt], ahi[mt], bhi[nt]);
                mma8(c[mt][nt], alo[mt], bhi[nt]);
                mma8(c[mt][nt], ahi[mt], blo[nt]);
            }
    }

    // epilogue: direct stores with bias
#pragma unroll
    for (int mt = 0; mt < 2; mt++) {
#pragma unroll
        for (int nt = 0; nt < 4; nt++) {
            int colBase = n0 + nt * 8 + 2 * lc;
            float b0 = __ldg(&bias[colBase]);
            float b1 = __ldg(&bias[colBase + 1]);
            int r0 = row0 + m0 + mt * 16 + lr;
            int r1 = r0 + 8;
            if (r0 < NN) {
                float2 o = make_float2(c[mt][nt][0] + b0, c[mt][nt][1] + b1);
                *(float2*)&out[(size_t)r0 * DD + colBase] = o;
            }
            if (r1 < NN) {
                float2 o = make_float2(c[mt][nt][2] + b0, c[mt][nt][3] + b1);
                *(float2*)&out[(size_t)r1 * DD + colBase] = o;
            }
        }
    }
}

// ---------------- launch ----------------
extern "C" void kernel_launch(void* const* d_in, const int* in_sizes, int n_in,
                              void* d_out, int out_size) {
    const float* x   = (const float*)d_in[0];
    const void*  ei  = d_in[1];
    const float* Wm  = (const float*)d_in[2];
    const float* bia = (const float*)d_in[3];
    float*       out = (float*)d_out;

    static bool attr_done = false;
    if (!attr_done) {
        cudaFuncSetAttribute(gemm_kernel, cudaFuncAttributeMaxDynamicSharedMemorySize,
                             GEMM_SMEM_BYTES);
        attr_done = true;
    }

    init_kernel<<<(NN + 255) / 256, 256>>>((const unsigned int*)ei);       // 1
    hist_kernel<<<(NE + 255) / 256, 256>>>(ei);                            // 2
    scale_kernel<<<(NN * 32 + 255) / 256, 256>>>((const float4*)x);        // 3
    scan_kernel<<<1, 1024>>>();                                            // 4
    scatter_kernel<<<(NE + 255) / 256, 256>>>(ei);                         // 5

    int prop_blocks = (NN * 32 + 255) / 256;
    prop1_kernel<<<prop_blocks, 256>>>();                                  // 6 (profiled)
    prop2_kernel<<<prop_blocks, 256>>>();                                  // 7
    gemm_kernel<<<(NN + 63) / 64, 256, GEMM_SMEM_BYTES>>>((const float4*)Wm, bia, out); // 8
}

// round 6
// speedup vs baseline: 2.0497x; 1.6695x over previous
#include <cuda_runtime.h>
#include <cuda_fp16.h>
#include <cstdint>

#define NN 100000
#define NE 1600000
#define DD 128
#define SCAN_BLOCKS ((NN + 255) / 256)   // 391

// ---------------- scratch ----------------
__device__ int   g_is64;
__device__ int   g_cnt[NN];
__device__ int   g_rowstart[NN + 1];
__device__ int   g_cursor[NN];
__device__ float g_dinv[NN];
__device__ int   g_src_sorted[NE];
__device__ unsigned long long g_bpack[SCAN_BLOCKS];  // (blockTotal<<32) | readyFlag
__device__ uint2  g_h0h[(size_t)NN * 32];  // x_hat = dinv*x, fp16
__device__ uint2  g_h1h[(size_t)NN * 32];  // h1_hat = dinv*h1, fp16
__device__ float4 g_h2[(size_t)NN * 32];   // h2, fp32

// ---------------- helpers ----------------
__device__ __forceinline__ float4 unpack_h4(uint2 u) {
    __half2 p0 = *(__half2*)&u.x;
    __half2 p1 = *(__half2*)&u.y;
    float2 f0 = __half22float2(p0);
    float2 f1 = __half22float2(p1);
    return make_float4(f0.x, f0.y, f1.x, f1.y);
}
__device__ __forceinline__ uint2 pack_h4(float a, float b, float c, float d) {
    __half2 p0 = __floats2half2_rn(a, b);
    __half2 p1 = __floats2half2_rn(c, d);
    uint2 u;
    u.x = *(unsigned*)&p0;
    u.y = *(unsigned*)&p1;
    return u;
}
__device__ __forceinline__ int load_idx(const void* ei, long long pos) {
    if (g_is64) return (int)((const long long*)ei)[pos];
    return ((const int*)ei)[pos];
}

// ---------------- 1) init: zero counters + scan flags + dtype detect ----------------
__global__ void init_kernel(const unsigned int* __restrict__ e) {
    int i = blockIdx.x * blockDim.x + threadIdx.x;
    if (i < NN) g_cnt[i] = 0;
    if (i < SCAN_BLOCKS) g_bpack[i] = 0ull;
    if (blockIdx.x == 0 && threadIdx.x == 0) {
        unsigned int odd_or = 0u;
        for (int j = 1; j < 2048; j += 2) odd_or |= e[j];
        g_is64 = (odd_or == 0u) ? 1 : 0;
    }
}

// ---------------- 2) histogram of dst ----------------
__global__ void hist_kernel(const void* __restrict__ ei) {
    int i = blockIdx.x * blockDim.x + threadIdx.x;
    if (i < NE) {
        int d = load_idx(ei, (long long)NE + i);
        if ((unsigned)d < (unsigned)NN) atomicAdd(&g_cnt[d], 1);
    }
}

// ---------------- 3) dinv + prescale x_hat = dinv*x (fp16) ----------------
__global__ void __launch_bounds__(256) scale_kernel(const float4* __restrict__ x) {
    int g = blockIdx.x * blockDim.x + threadIdx.x;
    int v = g >> 5, lane = g & 31;
    if (v >= NN) return;
    float dinv = rsqrtf((float)(g_cnt[v] + 1));
    if (lane == 0) g_dinv[v] = dinv;
    float4 a = x[(size_t)v * 32 + lane];
    g_h0h[(size_t)v * 32 + lane] = pack_h4(a.x * dinv, a.y * dinv, a.z * dinv, a.w * dinv);
}

// ---------------- 4) multi-block scan with decoupled lookback ----------------
__global__ void __launch_bounds__(256) scan_kernel() {
    __shared__ int wsum[8];
    __shared__ int s_off;

    int b = blockIdx.x;
    int t = threadIdx.x;
    int lane = t & 31, wid = t >> 5;
    int i = b * 256 + t;

    int c = (i < NN) ? g_cnt[i] : 0;

    // warp inclusive scan
    int v = c;
#pragma unroll
    for (int o = 1; o < 32; o <<= 1) {
        int n = __shfl_up_sync(0xffffffffu, v, o);
        if (lane >= o) v += n;
    }
    if (lane == 31) wsum[wid] = v;
    __syncthreads();
    if (t < 8) {
        int w = wsum[t];
#pragma unroll
        for (int o = 1; o < 8; o <<= 1) {
            int n = __shfl_up_sync(0xffu, w, o);
            if (t >= o) w += n;
        }
        wsum[t] = w;  // inclusive warp totals
    }
    __syncthreads();
    int incl = v + (wid ? wsum[wid - 1] : 0);
    int excl = incl - c;
    int blockTotal = wsum[7];

    // publish this block's aggregate (single aligned 64-bit store = atomic)
    if (t == 0) {
        *(volatile unsigned long long*)&g_bpack[b] =
            ((unsigned long long)(unsigned)blockTotal << 32) | 1ull;
    }

    // lookback: warp 0 sums all predecessor aggregates in parallel
    if (t < 32) {
        int sum = 0;
        for (int p = lane; p < b; p += 32) {
            unsigned long long pk;
            do {
                pk = *(volatile unsigned long long*)&g_bpack[p];
            } while ((pk & 1ull) == 0ull);
            sum += (int)(pk >> 32);
        }
#pragma unroll
        for (int o = 16; o; o >>= 1) sum += __shfl_down_sync(0xffffffffu, sum, o);
        if (t == 0) s_off = sum;
    }
    __syncthreads();

    int base = s_off + excl;
    if (i < NN) {
        g_rowstart[i] = base;
        g_cursor[i]   = base;
    }
    if (i == NN - 1) g_rowstart[NN] = base + c;
}

// ---------------- 5) scatter edges (src only; norm-free) ----------------
__global__ void scatter_kernel(const void* __restrict__ ei) {
    int i = blockIdx.x * blockDim.x + threadIdx.x;
    if (i < NE) {
        int s = load_idx(ei, i);
        int d = load_idx(ei, (long long)NE + i);
        if ((unsigned)s < (unsigned)NN && (unsigned)d < (unsigned)NN) {
            int p = atomicAdd(&g_cursor[d], 1);
            g_src_sorted[p] = s;
        }
    }
}

// ---------------- 6) propagation, warp per node, fp16 gather ----------------
__global__ void __launch_bounds__(256) prop1_kernel() {
    int g = blockIdx.x * blockDim.x + threadIdx.x;
    int v = g >> 5, lane = g & 31;
    if (v >= NN) return;
    float d = g_dinv[v];
    float sc = d * d;
    float4 acc = unpack_h4(g_h0h[(size_t)v * 32 + lane]);
    int e = g_rowstart[v], e1 = g_rowstart[v + 1];
    for (; e + 4 <= e1; e += 4) {
        int s0 = __ldg(&g_src_sorted[e]);
        int s1 = __ldg(&g_src_sorted[e + 1]);
        int s2 = __ldg(&g_src_sorted[e + 2]);
        int s3 = __ldg(&g_src_sorted[e + 3]);
        float4 a0 = unpack_h4(__ldg(&g_h0h[(size_t)s0 * 32 + lane]));
        float4 a1 = unpack_h4(__ldg(&g_h0h[(size_t)s1 * 32 + lane]));
        float4 a2 = unpack_h4(__ldg(&g_h0h[(size_t)s2 * 32 + lane]));
        float4 a3 = unpack_h4(__ldg(&g_h0h[(size_t)s3 * 32 + lane]));
        acc.x += a0.x + a1.x + a2.x + a3.x;
        acc.y += a0.y + a1.y + a2.y + a3.y;
        acc.z += a0.z + a1.z + a2.z + a3.z;
        acc.w += a0.w + a1.w + a2.w + a3.w;
    }
    for (; e < e1; e++) {
        int s = __ldg(&g_src_sorted[e]);
        float4 a = unpack_h4(__ldg(&g_h0h[(size_t)s * 32 + lane]));
        acc.x += a.x; acc.y += a.y; acc.z += a.z; acc.w += a.w;
    }
    g_h1h[(size_t)v * 32 + lane] = pack_h4(acc.x * sc, acc.y * sc, acc.z * sc, acc.w * sc);
}

__global__ void __launch_bounds__(256) prop2_kernel() {
    int g = blockIdx.x * blockDim.x + threadIdx.x;
    int v = g >> 5, lane = g & 31;
    if (v >= NN) return;
    float sc = g_dinv[v];
    float4 acc = unpack_h4(g_h1h[(size_t)v * 32 + lane]);
    int e = g_rowstart[v], e1 = g_rowstart[v + 1];
    for (; e + 4 <= e1; e += 4) {
        int s0 = __ldg(&g_src_sorted[e]);
        int s1 = __ldg(&g_src_sorted[e + 1]);
        int s2 = __ldg(&g_src_sorted[e + 2]);
        int s3 = __ldg(&g_src_sorted[e + 3]);
        float4 a0 = unpack_h4(__ldg(&g_h1h[(size_t)s0 * 32 + lane]));
        float4 a1 = unpack_h4(__ldg(&g_h1h[(size_t)s1 * 32 + lane]));
        float4 a2 = unpack_h4(__ldg(&g_h1h[(size_t)s2 * 32 + lane]));
        float4 a3 = unpack_h4(__ldg(&g_h1h[(size_t)s3 * 32 + lane]));
        acc.x += a0.x + a1.x + a2.x + a3.x;
        acc.y += a0.y + a1.y + a2.y + a3.y;
        acc.z += a0.z + a1.z + a2.z + a3.z;
        acc.w += a0.w + a1.w + a2.w + a3.w;
    }
    for (; e < e1; e++) {
        int s = __ldg(&g_src_sorted[e]);
        float4 a = unpack_h4(__ldg(&g_h1h[(size_t)s * 32 + lane]));
        acc.x += a.x; acc.y += a.y; acc.z += a.z; acc.w += a.w;
    }
    g_h2[(size_t)v * 32 + lane] = make_float4(acc.x * sc, acc.y * sc, acc.z * sc, acc.w * sc);
}

// ---------------- 7) GEMM via tf32 mma with 3-term split ----------------
#define AS_STRIDE 132
#define WS_STRIDE 136
#define GEMM_SMEM_BYTES ((64 * AS_STRIDE + 128 * WS_STRIDE) * 4)

__device__ __forceinline__ void mma8(float c[4], const unsigned a[4], const unsigned b[2]) {
    asm volatile(
        "mma.sync.aligned.m16n8k8.row.col.f32.tf32.tf32.f32 "
        "{%0,%1,%2,%3}, {%4,%5,%6,%7}, {%8,%9}, {%0,%1,%2,%3};\n"
        : "+f"(c[0]), "+f"(c[1]), "+f"(c[2]), "+f"(c[3])
        : "r"(a[0]), "r"(a[1]), "r"(a[2]), "r"(a[3]), "r"(b[0]), "r"(b[1]));
}
__device__ __forceinline__ void split_tf32(float x, unsigned& hi, unsigned& lo) {
    unsigned h;
    asm("cvt.rna.tf32.f32 %0, %1;" : "=r"(h) : "f"(x));
    hi = h;
    lo = __float_as_uint(x - __uint_as_float(h));
}

__global__ void __launch_bounds__(256) gemm_kernel(const float4* __restrict__ Wm,
                                                   const float* __restrict__ bias,
                                                   float* __restrict__ out) {
    extern __shared__ float smem[];
    float* As = smem;                       // [64][AS_STRIDE]
    float* Ws = smem + 64 * AS_STRIDE;      // [128][WS_STRIDE]

    int tid = threadIdx.x;
    int row0 = blockIdx.x * 64;

#pragma unroll
    for (int j = 0; j < 16; j++) {
        int idx = tid + j * 256;
        int r = idx >> 5;
        int c4 = idx & 31;
        float4 w = __ldg(&Wm[idx]);
        *(float4*)&Ws[r * WS_STRIDE + c4 * 4] = w;
    }
    const float4* A4 = (const float4*)g_h2;
#pragma unroll
    for (int j = 0; j < 8; j++) {
        int idx = tid + j * 256;
        int r = idx >> 5;
        int c4 = idx & 31;
        int gr = row0 + r;
        float4 a = (gr < NN) ? A4[(size_t)gr * 32 + c4] : make_float4(0.f, 0.f, 0.f, 0.f);
        *(float4*)&As[r * AS_STRIDE + c4 * 4] = a;
    }
    __syncthreads();

    int warp = tid >> 5, lane = tid & 31;
    int mwarp = warp & 1, nwarp = warp >> 1;
    int m0 = mwarp * 32, n0 = nwarp * 32;
    int lr = lane >> 2, lc = lane & 3;

    float c[2][4][4];
#pragma unroll
    for (int mt = 0; mt < 2; mt++)
#pragma unroll
        for (int nt = 0; nt < 4; nt++)
#pragma unroll
            for (int i = 0; i < 4; i++) c[mt][nt][i] = 0.f;

    for (int k0 = 0; k0 < 128; k0 += 8) {
        unsigned ahi[2][4], alo[2][4];
#pragma unroll
        for (int mt = 0; mt < 2; mt++) {
            int mb = m0 + mt * 16;
            float a0 = As[(mb + lr) * AS_STRIDE + k0 + lc];
            float a1 = As[(mb + lr + 8) * AS_STRIDE + k0 + lc];
            float a2 = As[(mb + lr) * AS_STRIDE + k0 + lc + 4];
            float a3 = As[(mb + lr + 8) * AS_STRIDE + k0 + lc + 4];
            split_tf32(a0, ahi[mt][0], alo[mt][0]);
            split_tf32(a1, ahi[mt][1], alo[mt][1]);
            split_tf32(a2, ahi[mt][2], alo[mt][2]);
            split_tf32(a3, ahi[mt][3], alo[mt][3]);
        }
        unsigned bhi[4][2], blo[4][2];
#pragma unroll
        for (int nt = 0; nt < 4; nt++) {
            int nb = n0 + nt * 8;
            float b0 = Ws[(k0 + lc) * WS_STRIDE + nb + lr];
            float b1 = Ws[(k0 + lc + 4) * WS_STRIDE + nb + lr];
            split_tf32(b0, bhi[nt][0], blo[nt][0]);
            split_tf32(b1, bhi[nt][1], blo[nt][1]);
        }
#pragma unroll
        for (int mt = 0; mt < 2; mt++)
#pragma unroll
            for (int nt = 0; nt < 4; nt++) {
                mma8(c[mt][nt], ahi[mt], bhi[nt]);
                mma8(c[mt][nt], alo[mt], bhi[nt]);
                mma8(c[mt][nt], ahi[mt], blo[nt]);
            }
    }

#pragma unroll
    for (int mt = 0; mt < 2; mt++) {
#pragma unroll
        for (int nt = 0; nt < 4; nt++) {
            int colBase = n0 + nt * 8 + 2 * lc;
            float b0 = __ldg(&bias[colBase]);
            float b1 = __ldg(&bias[colBase + 1]);
            int r0 = row0 + m0 + mt * 16 + lr;
            int r1 = r0 + 8;
            if (r0 < NN) {
                float2 o = make_float2(c[mt][nt][0] + b0, c[mt][nt][1] + b1);
                *(float2*)&out[(size_t)r0 * DD + colBase] = o;
            }
            if (r1 < NN) {
                float2 o = make_float2(c[mt][nt][2] + b0, c[mt][nt][3] + b1);
                *(float2*)&out[(size_t)r1 * DD + colBase] = o;
            }
        }
    }
}

// ---------------- launch ----------------
extern "C" void kernel_launch(void* const* d_in, const int* in_sizes, int n_in,
                              void* d_out, int out_size) {
    const float* x   = (const float*)d_in[0];
    const void*  ei  = d_in[1];
    const float* Wm  = (const float*)d_in[2];
    const float* bia = (const float*)d_in[3];
    float*       out = (float*)d_out;

    static bool attr_done = false;
    if (!attr_done) {
        cudaFuncSetAttribute(gemm_kernel, cudaFuncAttributeMaxDynamicSharedMemorySize,
                             GEMM_SMEM_BYTES);
        attr_done = true;
    }

    init_kernel<<<(NN + 255) / 256, 256>>>((const unsigned int*)ei);   // 1
    hist_kernel<<<(NE + 255) / 256, 256>>>(ei);                        // 2
    scale_kernel<<<(NN * 32 + 255) / 256, 256>>>((const float4*)x);    // 3
    scan_kernel<<<SCAN_BLOCKS, 256>>>();                               // 4 (profiled)
    scatter_kernel<<<(NE + 255) / 256, 256>>>(ei);                     // 5

    int prop_blocks = (NN * 32 + 255) / 256;
    prop1_kernel<<<prop_blocks, 256>>>();                              // 6
    prop2_kernel<<<prop_blocks, 256>>>();                              // 7
    gemm_kernel<<<(NN + 63) / 64, 256, GEMM_SMEM_BYTES>>>((const float4*)Wm, bia, out); // 8
}

// round 7
// speedup vs baseline: 2.0956x; 1.0224x over previous
#include <cuda_runtime.h>
#include <cuda_fp16.h>
#include <cstdint>

#define NN 100000
#define NE 1600000
#define DD 128
#define SCAN_BLOCKS ((NN + 255) / 256)   // 391

// ---------------- scratch ----------------
__device__ int   g_is64;
__device__ int   g_cnt[NN];
__device__ int   g_rowstart[NN + 1];
__device__ int   g_cursor[NN];
__device__ float g_dinv[NN];
__device__ int   g_src_sorted[NE];
__device__ unsigned long long g_bpack[SCAN_BLOCKS];
__device__ uint4 g_h0h[(size_t)NN * 16];  // x_hat  fp16, 16B granules (8 halves)
__device__ uint4 g_h1h[(size_t)NN * 16];  // h1_hat fp16
__device__ uint4 g_h2h[(size_t)NN * 16];  // h2     fp16

// ---------------- helpers ----------------
__device__ __forceinline__ void unpack8(uint4 u, float f[8]) {
    float2 a = __half22float2(*(__half2*)&u.x);
    float2 b = __half22float2(*(__half2*)&u.y);
    float2 c = __half22float2(*(__half2*)&u.z);
    float2 d = __half22float2(*(__half2*)&u.w);
    f[0] = a.x; f[1] = a.y; f[2] = b.x; f[3] = b.y;
    f[4] = c.x; f[5] = c.y; f[6] = d.x; f[7] = d.y;
}
__device__ __forceinline__ uint4 pack8(const float f[8], float s) {
    __half2 a = __floats2half2_rn(f[0] * s, f[1] * s);
    __half2 b = __floats2half2_rn(f[2] * s, f[3] * s);
    __half2 c = __floats2half2_rn(f[4] * s, f[5] * s);
    __half2 d = __floats2half2_rn(f[6] * s, f[7] * s);
    uint4 u;
    u.x = *(unsigned*)&a; u.y = *(unsigned*)&b;
    u.z = *(unsigned*)&c; u.w = *(unsigned*)&d;
    return u;
}
__device__ __forceinline__ int load_idx(const void* ei, long long pos) {
    if (g_is64) return (int)((const long long*)ei)[pos];
    return ((const int*)ei)[pos];
}

// ---------------- 1) init ----------------
__global__ void init_kernel(const unsigned int* __restrict__ e) {
    int i = blockIdx.x * blockDim.x + threadIdx.x;
    if (i < NN) g_cnt[i] = 0;
    if (i < SCAN_BLOCKS) g_bpack[i] = 0ull;
    if (blockIdx.x == 0 && threadIdx.x == 0) {
        unsigned int odd_or = 0u;
        for (int j = 1; j < 2048; j += 2) odd_or |= e[j];
        g_is64 = (odd_or == 0u) ? 1 : 0;
    }
}

// ---------------- 2) histogram of dst ----------------
__global__ void hist_kernel(const void* __restrict__ ei) {
    int i = blockIdx.x * blockDim.x + threadIdx.x;
    if (i < NE) {
        int d = load_idx(ei, (long long)NE + i);
        if ((unsigned)d < (unsigned)NN) atomicAdd(&g_cnt[d], 1);
    }
}

// ---------------- 3) dinv + prescale x_hat = dinv*x (fp16) ----------------
__global__ void __launch_bounds__(256) scale_kernel(const float4* __restrict__ x) {
    int g = blockIdx.x * blockDim.x + threadIdx.x;
    int v = g >> 4, lane = g & 15;          // 16 lanes/node, 8 floats/lane
    if (v >= NN) return;
    float dinv = rsqrtf((float)(g_cnt[v] + 1));
    if (lane == 0) g_dinv[v] = dinv;
    float4 a = x[(size_t)v * 32 + lane * 2];
    float4 b = x[(size_t)v * 32 + lane * 2 + 1];
    float f[8] = {a.x, a.y, a.z, a.w, b.x, b.y, b.z, b.w};
    g_h0h[(size_t)v * 16 + lane] = pack8(f, dinv);
}

// ---------------- 4) multi-block scan with decoupled lookback ----------------
__global__ void __launch_bounds__(256) scan_kernel() {
    __shared__ int wsum[8];
    __shared__ int s_off;

    int b = blockIdx.x;
    int t = threadIdx.x;
    int lane = t & 31, wid = t >> 5;
    int i = b * 256 + t;

    int c = (i < NN) ? g_cnt[i] : 0;
    int v = c;
#pragma unroll
    for (int o = 1; o < 32; o <<= 1) {
        int n = __shfl_up_sync(0xffffffffu, v, o);
        if (lane >= o) v += n;
    }
    if (lane == 31) wsum[wid] = v;
    __syncthreads();
    if (t < 8) {
        int w = wsum[t];
#pragma unroll
        for (int o = 1; o < 8; o <<= 1) {
            int n = __shfl_up_sync(0xffu, w, o);
            if (t >= o) w += n;
        }
        wsum[t] = w;
    }
    __syncthreads();
    int incl = v + (wid ? wsum[wid - 1] : 0);
    int excl = incl - c;
    int blockTotal = wsum[7];

    if (t == 0) {
        *(volatile unsigned long long*)&g_bpack[b] =
            ((unsigned long long)(unsigned)blockTotal << 32) | 1ull;
    }
    if (t < 32) {
        int sum = 0;
        for (int p = lane; p < b; p += 32) {
            unsigned long long pk;
            do {
                pk = *(volatile unsigned long long*)&g_bpack[p];
            } while ((pk & 1ull) == 0ull);
            sum += (int)(pk >> 32);
        }
#pragma unroll
        for (int o = 16; o; o >>= 1) sum += __shfl_down_sync(0xffffffffu, sum, o);
        if (t == 0) s_off = sum;
    }
    __syncthreads();

    int base = s_off + excl;
    if (i < NN) {
        g_rowstart[i] = base;
        g_cursor[i]   = base;
    }
    if (i == NN - 1) g_rowstart[NN] = base + c;
}

// ---------------- 5) scatter edges ----------------
__global__ void scatter_kernel(const void* __restrict__ ei) {
    int i = blockIdx.x * blockDim.x + threadIdx.x;
    if (i < NE) {
        int s = load_idx(ei, i);
        int d = load_idx(ei, (long long)NE + i);
        if ((unsigned)s < (unsigned)NN && (unsigned)d < (unsigned)NN) {
            int p = atomicAdd(&g_cursor[d], 1);
            g_src_sorted[p] = s;
        }
    }
}

// ---------------- 6) propagation: 16 lanes/node, 2 nodes/warp ----------------
// hin/hout are uint4 fp16 rows (16 x uint4 per node).
// out[v] = scale(v) * (hin[v] + sum_src hin[src])
template <bool SQ>
__device__ __forceinline__ void prop_body16(const uint4* __restrict__ hin,
                                            uint4* __restrict__ hout) {
    int g = blockIdx.x * blockDim.x + threadIdx.x;
    int v = g >> 4, lane = g & 15;
    if (v >= NN) return;

    float d = g_dinv[v];
    float sc = SQ ? d * d : d;

    float acc[8];
    unpack8(hin[(size_t)v * 16 + lane], acc);

    int e = g_rowstart[v], e1 = g_rowstart[v + 1];
    for (; e + 4 <= e1; e += 4) {
        int s0 = __ldg(&g_src_sorted[e]);
        int s1 = __ldg(&g_src_sorted[e + 1]);
        int s2 = __ldg(&g_src_sorted[e + 2]);
        int s3 = __ldg(&g_src_sorted[e + 3]);
        uint4 u0 = __ldg(&hin[(size_t)s0 * 16 + lane]);
        uint4 u1 = __ldg(&hin[(size_t)s1 * 16 + lane]);
        uint4 u2 = __ldg(&hin[(size_t)s2 * 16 + lane]);
        uint4 u3 = __ldg(&hin[(size_t)s3 * 16 + lane]);
        float f0[8], f1[8], f2[8], f3[8];
        unpack8(u0, f0); unpack8(u1, f1); unpack8(u2, f2); unpack8(u3, f3);
#pragma unroll
        for (int k = 0; k < 8; k++) acc[k] += (f0[k] + f1[k]) + (f2[k] + f3[k]);
    }
    for (; e < e1; e++) {
        int s = __ldg(&g_src_sorted[e]);
        uint4 u = __ldg(&hin[(size_t)s * 16 + lane]);
        float f[8];
        unpack8(u, f);
#pragma unroll
        for (int k = 0; k < 8; k++) acc[k] += f[k];
    }
    hout[(size_t)v * 16 + lane] = pack8(acc, sc);
}

__global__ void __launch_bounds__(256) prop1_kernel() { prop_body16<true>(g_h0h, g_h1h); }
__global__ void __launch_bounds__(256) prop2_kernel() { prop_body16<false>(g_h1h, g_h2h); }

// ---------------- 7) GEMM via tf32 mma with 3-term split (A in fp16) -------
#define AS_STRIDE 132
#define WS_STRIDE 136
#define GEMM_SMEM_BYTES ((64 * AS_STRIDE + 128 * WS_STRIDE) * 4)

__device__ __forceinline__ void mma8(float c[4], const unsigned a[4], const unsigned b[2]) {
    asm volatile(
        "mma.sync.aligned.m16n8k8.row.col.f32.tf32.tf32.f32 "
        "{%0,%1,%2,%3}, {%4,%5,%6,%7}, {%8,%9}, {%0,%1,%2,%3};\n"
        : "+f"(c[0]), "+f"(c[1]), "+f"(c[2]), "+f"(c[3])
        : "r"(a[0]), "r"(a[1]), "r"(a[2]), "r"(a[3]), "r"(b[0]), "r"(b[1]));
}
__device__ __forceinline__ void split_tf32(float x, unsigned& hi, unsigned& lo) {
    unsigned h;
    asm("cvt.rna.tf32.f32 %0, %1;" : "=r"(h) : "f"(x));
    hi = h;
    lo = __float_as_uint(x - __uint_as_float(h));
}

__global__ void __launch_bounds__(256) gemm_kernel(const float4* __restrict__ Wm,
                                                   const float* __restrict__ bias,
                                                   float* __restrict__ out) {
    extern __shared__ float smem[];
    float* As = smem;                       // [64][AS_STRIDE]
    float* Ws = smem + 64 * AS_STRIDE;      // [128][WS_STRIDE]

    int tid = threadIdx.x;
    int row0 = blockIdx.x * 64;

#pragma unroll
    for (int j = 0; j < 16; j++) {
        int idx = tid + j * 256;
        int r = idx >> 5;
        int c4 = idx & 31;
        float4 w = __ldg(&Wm[idx]);
        *(float4*)&Ws[r * WS_STRIDE + c4 * 4] = w;
    }
    // A tile 64x128 from fp16 h2: per thread 8 uint2 (4 halves each)
    const uint2* A2 = (const uint2*)g_h2h;
#pragma unroll
    for (int j = 0; j < 8; j++) {
        int idx = tid + j * 256;           // 0..2047 over 64 rows x 32 uint2
        int r = idx >> 5;
        int c4 = idx & 31;                 // 4-half granule
        int gr = row0 + r;
        uint2 u = (gr < NN) ? __ldg(&A2[(size_t)gr * 32 + c4]) : make_uint2(0u, 0u);
        float2 f0 = __half22float2(*(__half2*)&u.x);
        float2 f1 = __half22float2(*(__half2*)&u.y);
        float4 a = make_float4(f0.x, f0.y, f1.x, f1.y);
        *(float4*)&As[r * AS_STRIDE + c4 * 4] = a;
    }
    __syncthreads();

    int warp = tid >> 5, lane = tid & 31;
    int mwarp = warp & 1, nwarp = warp >> 1;
    int m0 = mwarp * 32, n0 = nwarp * 32;
    int lr = lane >> 2, lc = lane & 3;

    float c[2][4][4];
#pragma unroll
    for (int mt = 0; mt < 2; mt++)
#pragma unroll
        for (int nt = 0; nt < 4; nt++)
#pragma unroll
            for (int i = 0; i < 4; i++) c[mt][nt][i] = 0.f;

    for (int k0 = 0; k0 < 128; k0 += 8) {
        unsigned ahi[2][4], alo[2][4];
#pragma unroll
        for (int mt = 0; mt < 2; mt++) {
            int mb = m0 + mt * 16;
            float a0 = As[(mb + lr) * AS_STRIDE + k0 + lc];
            float a1 = As[(mb + lr + 8) * AS_STRIDE + k0 + lc];
            float a2 = As[(mb + lr) * AS_STRIDE + k0 + lc + 4];
            float a3 = As[(mb + lr + 8) * AS_STRIDE + k0 + lc + 4];
            split_tf32(a0, ahi[mt][0], alo[mt][0]);
            split_tf32(a1, ahi[mt][1], alo[mt][1]);
            split_tf32(a2, ahi[mt][2], alo[mt][2]);
            split_tf32(a3, ahi[mt][3], alo[mt][3]);
        }
        unsigned bhi[4][2], blo[4][2];
#pragma unroll
        for (int nt = 0; nt < 4; nt++) {
            int nb = n0 + nt * 8;
            float b0 = Ws[(k0 + lc) * WS_STRIDE + nb + lr];
            float b1 = Ws[(k0 + lc + 4) * WS_STRIDE + nb + lr];
            split_tf32(b0, bhi[nt][0], blo[nt][0]);
            split_tf32(b1, bhi[nt][1], blo[nt][1]);
        }
#pragma unroll
        for (int mt = 0; mt < 2; mt++)
#pragma unroll
            for (int nt = 0; nt < 4; nt++) {
                mma8(c[mt][nt], ahi[mt], bhi[nt]);
                mma8(c[mt][nt], alo[mt], bhi[nt]);
                mma8(c[mt][nt], ahi[mt], blo[nt]);
            }
    }

#pragma unroll
    for (int mt = 0; mt < 2; mt++) {
#pragma unroll
        for (int nt = 0; nt < 4; nt++) {
            int colBase = n0 + nt * 8 + 2 * lc;
            float b0 = __ldg(&bias[colBase]);
            float b1 = __ldg(&bias[colBase + 1]);
            int r0 = row0 + m0 + mt * 16 + lr;
            int r1 = r0 + 8;
            if (r0 < NN) {
                float2 o = make_float2(c[mt][nt][0] + b0, c[mt][nt][1] + b1);
                *(float2*)&out[(size_t)r0 * DD + colBase] = o;
            }
            if (r1 < NN) {
                float2 o = make_float2(c[mt][nt][2] + b0, c[mt][nt][3] + b1);
                *(float2*)&out[(size_t)r1 * DD + colBase] = o;
            }
        }
    }
}

// ---------------- launch ----------------
extern "C" void kernel_launch(void* const* d_in, const int* in_sizes, int n_in,
                              void* d_out, int out_size) {
    const float* x   = (const float*)d_in[0];
    const void*  ei  = d_in[1];
    const float* Wm  = (const float*)d_in[2];
    const float* bia = (const float*)d_in[3];
    float*       out = (float*)d_out;

    static bool attr_done = false;
    if (!attr_done) {
        cudaFuncSetAttribute(gemm_kernel, cudaFuncAttributeMaxDynamicSharedMemorySize,
                             GEMM_SMEM_BYTES);
        attr_done = true;
    }

    init_kernel<<<(NN + 255) / 256, 256>>>((const unsigned int*)ei);   // 1
    hist_kernel<<<(NE + 255) / 256, 256>>>(ei);                        // 2
    scale_kernel<<<(NN * 16 + 255) / 256, 256>>>((const float4*)x);    // 3
    scan_kernel<<<SCAN_BLOCKS, 256>>>();                               // 4
    scatter_kernel<<<(NE + 255) / 256, 256>>>(ei);                     // 5

    int prop_blocks = (NN * 16 + 255) / 256;                           // 16 lanes/node
    prop1_kernel<<<prop_blocks, 256>>>();                              // 6
    prop2_kernel<<<prop_blocks, 256>>>();                              // 7
    gemm_kernel<<<(NN + 63) / 64, 256, GEMM_SMEM_BYTES>>>((const float4*)Wm, bia, out); // 8
}

// round 8
// speedup vs baseline: 2.3832x; 1.1372x over previous
#include <cuda_runtime.h>
#include <cuda_fp16.h>
#include <cstdint>

#define NN 100000
#define NE 1600000
#define DD 128
#define SCAN_BLOCKS ((NN + 255) / 256)     // 391
#define SCALE_BLOCKS ((NN * 16 + 255) / 256) // 6250

// ---------------- scratch (zero-initialized at module load) ----------------
__device__ int   g_cnt[NN];
__device__ int   g_rowstart[NN + 1];
__device__ int   g_cursor[NN];
__device__ float g_dinv[NN];
__device__ int   g_src_sorted[NE];
__device__ unsigned long long g_bpack[SCAN_BLOCKS];
__device__ int   g_ticket;
__device__ uint4 g_h0h[(size_t)NN * 16];  // x_hat  fp16 (8 halves / uint4)
__device__ uint4 g_h1h[(size_t)NN * 16];  // h1_hat fp16
__device__ uint4 g_h2h[(size_t)NN * 16];  // h2     fp16

// ---------------- helpers ----------------
__device__ __forceinline__ void unpack8(uint4 u, float f[8]) {
    float2 a = __half22float2(*(__half2*)&u.x);
    float2 b = __half22float2(*(__half2*)&u.y);
    float2 c = __half22float2(*(__half2*)&u.z);
    float2 d = __half22float2(*(__half2*)&u.w);
    f[0] = a.x; f[1] = a.y; f[2] = b.x; f[3] = b.y;
    f[4] = c.x; f[5] = c.y; f[6] = d.x; f[7] = d.y;
}
__device__ __forceinline__ uint4 pack8(const float f[8], float s) {
    __half2 a = __floats2half2_rn(f[0] * s, f[1] * s);
    __half2 b = __floats2half2_rn(f[2] * s, f[3] * s);
    __half2 c = __floats2half2_rn(f[4] * s, f[5] * s);
    __half2 d = __floats2half2_rn(f[6] * s, f[7] * s);
    uint4 u;
    u.x = *(unsigned*)&a; u.y = *(unsigned*)&b;
    u.z = *(unsigned*)&c; u.w = *(unsigned*)&d;
    return u;
}

// block-local dtype detect: int64 little-endian => all odd 32-bit words zero
__device__ __forceinline__ int block_is64(const unsigned int* e) {
    unsigned m = 0;
    int t = threadIdx.x;
    for (int k = t; k < 1024; k += 256) m |= e[2 * k + 1];
    return __syncthreads_or((int)m) == 0;
}
__device__ __forceinline__ int load_idx(const void* ei, long long pos, int is64) {
    if (is64) return (int)((const long long*)ei)[pos];
    return ((const int*)ei)[pos];
}

// ---------------- 1) histogram of dst (cnt zero on entry, restored later) ----
__global__ void __launch_bounds__(256) hist_kernel(const void* __restrict__ ei) {
    int is64 = block_is64((const unsigned int*)ei);
    int i = blockIdx.x * blockDim.x + threadIdx.x;
    if (i < NE) {
        int d = load_idx(ei, (long long)NE + i, is64);
        if ((unsigned)d < (unsigned)NN) atomicAdd(&g_cnt[d], 1);
    }
}

// ---------------- 2) fused: decoupled-lookback scan  |  x prescale ---------
__global__ void __launch_bounds__(256) scan_scale_kernel(const float4* __restrict__ x) {
    int t = threadIdx.x;
    if (blockIdx.x < SCAN_BLOCKS) {
        // ---- scan part (ticketed virtual block id) ----
        __shared__ int s_b;
        __shared__ int wsum[8];
        __shared__ int s_off;
        if (t == 0) s_b = atomicAdd(&g_ticket, 1);
        __syncthreads();
        int b = s_b;
        int lane = t & 31, wid = t >> 5;
        int i = b * 256 + t;

        int c = (i < NN) ? g_cnt[i] : 0;
        int v = c;
#pragma unroll
        for (int o = 1; o < 32; o <<= 1) {
            int n = __shfl_up_sync(0xffffffffu, v, o);
            if (lane >= o) v += n;
        }
        if (lane == 31) wsum[wid] = v;
        __syncthreads();
        if (t < 8) {
            int w = wsum[t];
#pragma unroll
            for (int o = 1; o < 8; o <<= 1) {
                int n = __shfl_up_sync(0xffu, w, o);
                if (t >= o) w += n;
            }
            wsum[t] = w;
        }
        __syncthreads();
        int incl = v + (wid ? wsum[wid - 1] : 0);
        int excl = incl - c;
        int blockTotal = wsum[7];

        if (t == 0) {
            *(volatile unsigned long long*)&g_bpack[b] =
                ((unsigned long long)(unsigned)blockTotal << 32) | 1ull;
        }
        if (t < 32) {
            int sum = 0;
            for (int p = lane; p < b; p += 32) {
                unsigned long long pk;
                do {
                    pk = *(volatile unsigned long long*)&g_bpack[p];
                } while ((pk & 1ull) == 0ull);
                sum += (int)(pk >> 32);
            }
#pragma unroll
            for (int o = 16; o; o >>= 1) sum += __shfl_down_sync(0xffffffffu, sum, o);
            if (t == 0) s_off = sum;
        }
        __syncthreads();

        int base = s_off + excl;
        if (i < NN) {
            g_rowstart[i] = base;
            g_cursor[i]   = base;
        }
        if (i == NN - 1) g_rowstart[NN] = base + c;
    } else {
        // ---- prescale part: x_hat = dinv*x (fp16); dinv from cnt directly ----
        int idx = (blockIdx.x - SCAN_BLOCKS) * 256 + t;
        int v = idx >> 4, lane = idx & 15;
        if (v >= NN) return;
        float dinv = rsqrtf((float)(g_cnt[v] + 1));
        if (lane == 0) g_dinv[v] = dinv;
        float4 a = x[(size_t)v * 32 + lane * 2];
        float4 b4 = x[(size_t)v * 32 + lane * 2 + 1];
        float f[8] = {a.x, a.y, a.z, a.w, b4.x, b4.y, b4.z, b4.w};
        g_h0h[(size_t)v * 16 + lane] = pack8(f, dinv);
    }
}

// ---------------- 3) scatter edges + restore zero-state for next replay ----
__global__ void __launch_bounds__(256) scatter_kernel(const void* __restrict__ ei) {
    int is64 = block_is64((const unsigned int*)ei);
    int i = blockIdx.x * blockDim.x + threadIdx.x;
    // restore the zero invariants consumed by hist/scan (safe: cnt/bpack/ticket
    // have no readers after the scan_scale launch)
    if (i < NN) g_cnt[i] = 0;
    if (i < SCAN_BLOCKS) g_bpack[i] = 0ull;
    if (i == 0) g_ticket = 0;
    if (i < NE) {
        int s = load_idx(ei, i, is64);
        int d = load_idx(ei, (long long)NE + i, is64);
        if ((unsigned)s < (unsigned)NN && (unsigned)d < (unsigned)NN) {
            int p = atomicAdd(&g_cursor[d], 1);
            g_src_sorted[p] = s;
        }
    }
}

// ---------------- 4/5) propagation: 16 lanes/node, unroll 8 ----------------
template <bool SQ>
__device__ __forceinline__ void prop_body16(const uint4* __restrict__ hin,
                                            uint4* __restrict__ hout) {
    int g = blockIdx.x * blockDim.x + threadIdx.x;
    int v = g >> 4, lane = g & 15;
    if (v >= NN) return;

    float d = g_dinv[v];
    float sc = SQ ? d * d : d;

    float acc[8];
    unpack8(hin[(size_t)v * 16 + lane], acc);

    int e = g_rowstart[v], e1 = g_rowstart[v + 1];

    for (; e + 8 <= e1; e += 8) {
        int s[8];
#pragma unroll
        for (int k = 0; k < 8; k++) s[k] = __ldg(&g_src_sorted[e + k]);
        uint4 u[8];
#pragma unroll
        for (int k = 0; k < 8; k++) u[k] = __ldg(&hin[(size_t)s[k] * 16 + lane]);
#pragma unroll
        for (int k = 0; k < 8; k++) {
            float f[8];
            unpack8(u[k], f);
#pragma unroll
            for (int j = 0; j < 8; j++) acc[j] += f[j];
        }
    }
    for (; e + 2 <= e1; e += 2) {
        int s0 = __ldg(&g_src_sorted[e]);
        int s1 = __ldg(&g_src_sorted[e + 1]);
        uint4 u0 = __ldg(&hin[(size_t)s0 * 16 + lane]);
        uint4 u1 = __ldg(&hin[(size_t)s1 * 16 + lane]);
        float f0[8], f1[8];
        unpack8(u0, f0); unpack8(u1, f1);
#pragma unroll
        for (int j = 0; j < 8; j++) acc[j] += f0[j] + f1[j];
    }
    if (e < e1) {
        int s = __ldg(&g_src_sorted[e]);
        uint4 u = __ldg(&hin[(size_t)s * 16 + lane]);
        float f[8];
        unpack8(u, f);
#pragma unroll
        for (int j = 0; j < 8; j++) acc[j] += f[j];
    }
    hout[(size_t)v * 16 + lane] = pack8(acc, sc);
}

__global__ void __launch_bounds__(256) prop1_kernel() { prop_body16<true>(g_h0h, g_h1h); }
__global__ void __launch_bounds__(256) prop2_kernel() { prop_body16<false>(g_h1h, g_h2h); }

// ---------------- 6) GEMM via tf32 mma with 3-term split (A in fp16) -------
#define AS_STRIDE 132
#define WS_STRIDE 136
#define GEMM_SMEM_BYTES ((64 * AS_STRIDE + 128 * WS_STRIDE) * 4)

__device__ __forceinline__ void mma8(float c[4], const unsigned a[4], const unsigned b[2]) {
    asm volatile(
        "mma.sync.aligned.m16n8k8.row.col.f32.tf32.tf32.f32 "
        "{%0,%1,%2,%3}, {%4,%5,%6,%7}, {%8,%9}, {%0,%1,%2,%3};\n"
        : "+f"(c[0]), "+f"(c[1]), "+f"(c[2]), "+f"(c[3])
        : "r"(a[0]), "r"(a[1]), "r"(a[2]), "r"(a[3]), "r"(b[0]), "r"(b[1]));
}
__device__ __forceinline__ void split_tf32(float x, unsigned& hi, unsigned& lo) {
    unsigned h;
    asm("cvt.rna.tf32.f32 %0, %1;" : "=r"(h) : "f"(x));
    hi = h;
    lo = __float_as_uint(x - __uint_as_float(h));
}

__global__ void __launch_bounds__(256) gemm_kernel(const float4* __restrict__ Wm,
                                                   const float* __restrict__ bias,
                                                   float* __restrict__ out) {
    extern __shared__ float smem[];
    float* As = smem;                       // [64][AS_STRIDE]
    float* Ws = smem + 64 * AS_STRIDE;      // [128][WS_STRIDE]

    int tid = threadIdx.x;
    int row0 = blockIdx.x * 64;

#pragma unroll
    for (int j = 0; j < 16; j++) {
        int idx = tid + j * 256;
        int r = idx >> 5;
        int c4 = idx & 31;
        float4 w = __ldg(&Wm[idx]);
        *(float4*)&Ws[r * WS_STRIDE + c4 * 4] = w;
    }
    const uint2* A2 = (const uint2*)g_h2h;
#pragma unroll
    for (int j = 0; j < 8; j++) {
        int idx = tid + j * 256;
        int r = idx >> 5;
        int c4 = idx & 31;
        int gr = row0 + r;
        uint2 u = (gr < NN) ? __ldg(&A2[(size_t)gr * 32 + c4]) : make_uint2(0u, 0u);
        float2 f0 = __half22float2(*(__half2*)&u.x);
        float2 f1 = __half22float2(*(__half2*)&u.y);
        float4 a = make_float4(f0.x, f0.y, f1.x, f1.y);
        *(float4*)&As[r * AS_STRIDE + c4 * 4] = a;
    }
    __syncthreads();

    int warp = tid >> 5, lane = tid & 31;
    int mwarp = warp & 1, nwarp = warp >> 1;
    int m0 = mwarp * 32, n0 = nwarp * 32;
    int lr = lane >> 2, lc = lane & 3;

    float c[2][4][4];
#pragma unroll
    for (int mt = 0; mt < 2; mt++)
#pragma unroll
        for (int nt = 0; nt < 4; nt++)
#pragma unroll
            for (int i = 0; i < 4; i++) c[mt][nt][i] = 0.f;

    for (int k0 = 0; k0 < 128; k0 += 8) {
        unsigned ahi[2][4], alo[2][4];
#pragma unroll
        for (int mt = 0; mt < 2; mt++) {
            int mb = m0 + mt * 16;
            float a0 = As[(mb + lr) * AS_STRIDE + k0 + lc];
            float a1 = As[(mb + lr + 8) * AS_STRIDE + k0 + lc];
            float a2 = As[(mb + lr) * AS_STRIDE + k0 + lc + 4];
            float a3 = As[(mb + lr + 8) * AS_STRIDE + k0 + lc + 4];
            split_tf32(a0, ahi[mt][0], alo[mt][0]);
            split_tf32(a1, ahi[mt][1], alo[mt][1]);
            split_tf32(a2, ahi[mt][2], alo[mt][2]);
            split_tf32(a3, ahi[mt][3], alo[mt][3]);
        }
        unsigned bhi[4][2], blo[4][2];
#pragma unroll
        for (int nt = 0; nt < 4; nt++) {
            int nb = n0 + nt * 8;
            float b0 = Ws[(k0 + lc) * WS_STRIDE + nb + lr];
            float b1 = Ws[(k0 + lc + 4) * WS_STRIDE + nb + lr];
            split_tf32(b0, bhi[nt][0], blo[nt][0]);
            split_tf32(b1, bhi[nt][1], blo[nt][1]);
        }
#pragma unroll
        for (int mt = 0; mt < 2; mt++)
#pragma unroll
            for (int nt = 0; nt < 4; nt++) {
                mma8(c[mt][nt], ahi[mt], bhi[nt]);
                mma8(c[mt][nt], alo[mt], bhi[nt]);
                mma8(c[mt][nt], ahi[mt], blo[nt]);
            }
    }

#pragma unroll
    for (int mt = 0; mt < 2; mt++) {
#pragma unroll
        for (int nt = 0; nt < 4; nt++) {
            int colBase = n0 + nt * 8 + 2 * lc;
            float b0 = __ldg(&bias[colBase]);
            float b1 = __ldg(&bias[colBase + 1]);
            int r0 = row0 + m0 + mt * 16 + lr;
            int r1 = r0 + 8;
            if (r0 < NN) {
                float2 o = make_float2(c[mt][nt][0] + b0, c[mt][nt][1] + b1);
                *(float2*)&out[(size_t)r0 * DD + colBase] = o;
            }
            if (r1 < NN) {
                float2 o = make_float2(c[mt][nt][2] + b0, c[mt][nt][3] + b1);
                *(float2*)&out[(size_t)r1 * DD + colBase] = o;
            }
        }
    }
}

// ---------------- launch ----------------
extern "C" void kernel_launch(void* const* d_in, const int* in_sizes, int n_in,
                              void* d_out, int out_size) {
    const float* x   = (const float*)d_in[0];
    const void*  ei  = d_in[1];
    const float* Wm  = (const float*)d_in[2];
    const float* bia = (const float*)d_in[3];
    float*       out = (float*)d_out;

    static bool attr_done = false;
    if (!attr_done) {
        cudaFuncSetAttribute(gemm_kernel, cudaFuncAttributeMaxDynamicSharedMemorySize,
                             GEMM_SMEM_BYTES);
        attr_done = true;
    }

    hist_kernel<<<(NE + 255) / 256, 256>>>(ei);                               // 1
    scan_scale_kernel<<<SCAN_BLOCKS + SCALE_BLOCKS, 256>>>((const float4*)x); // 2
    scatter_kernel<<<(NE + 255) / 256, 256>>>(ei);                            // 3

    int prop_blocks = (NN * 16 + 255) / 256;
    prop1_kernel<<<prop_blocks, 256>>>();                                     // 4 (profiled)
    prop2_kernel<<<prop_blocks, 256>>>();                                     // 5
    gemm_kernel<<<(NN + 63) / 64, 256, GEMM_SMEM_BYTES>>>((const float4*)Wm, bia, out); // 6
}